// round 12
// baseline (speedup 1.0000x reference)
#include <cuda_runtime.h>

// B-spline layer, single fused kernel, short-critical-path version.
// out[b,f] = ((q3*u+q2)*u+q1)*u + q0,  u = 55x - ii, ii = floor(55x) in [0,54],
// q_d[ii,f] = sum_r P[ii][r][d] * C[ii+3+r, f]   (bias folded into q0).
// P = Cox-de Boor basis polynomial coefficients in local coord u, computed on
// the HOST in double (knot-only, deterministic), passed in the const bank.
//
// Cvt-free interval math: m = fmaf(x,55,2^23) -> mantissa = round(55x) (exact,
// spacing 1 in [2^23, 2^23+55]); branchless floor fixup via sign of 55x-n.
//
// Fold is FULLY UNROLLED to 4 predicated entries/thread so all 16 C-loads
// issue before any dependent FMA (one L2 round-trip of exposed latency
// instead of 3.4). Grid (64,8) = 512 blocks x 512 thr, 64 rows/block.

#define NF 256
#define NBATCH 4096
#define NII 55
#define NTHREADS 512
#define ROWS_PER_BLOCK 64
#define TABN (NII * 32)           // 1760 float4

struct PTab { float p[NII][4][4]; };

// ---------------- host-side knot/coefficient math (double) ----------------
static double knotD_h(int idx) {
    if (idx < 6)  return -0.002 + 0.0005 * (double)(idx - 3);
    if (idx > 61) return 1.001  + 0.0005 * (double)(idx - 62);
    return (double)(idx - 6) / 55.0;
}

static void make_ptab(PTab& T) {
    for (int ii = 0; ii < NII; ++ii) {
        const int j = ii + 6;
        double P[4][4] = {};
        P[0][0] = 1.0;
        const double x0 = (double)ii / 55.0;
        const double bs = 1.0 / 55.0;   // x = x0 + bs*u
        for (int k = 1; k <= 3; ++k) {
            double Q[4][4] = {};
            for (int r = 0; r <= k; ++r) {
                const int i = j - k + r;
                if (r >= 1) {
                    const double inv = 1.0 / (knotD_h(i + k) - knotD_h(i));
                    const double a = (x0 - knotD_h(i)) * inv;
                    const double b = bs * inv;
                    for (int d = 0; d < 4; ++d) {
                        Q[r][d] += a * P[r - 1][d];
                        if (d > 0) Q[r][d] += b * P[r - 1][d - 1];
                    }
                }
                if (r <= k - 1) {
                    const double inv = 1.0 / (knotD_h(i + k + 1) - knotD_h(i + 1));
                    const double a = (knotD_h(i + k + 1) - x0) * inv;
                    const double b = -bs * inv;
                    for (int d = 0; d < 4; ++d) {
                        Q[r][d] += a * P[r][d];
                        if (d > 0) Q[r][d] += b * P[r][d - 1];
                    }
                }
            }
            for (int r = 0; r < 4; ++r)
                for (int d = 0; d < 4; ++d) P[r][d] = Q[r][d];
        }
        for (int r = 0; r < 4; ++r)
            for (int d = 0; d < 4; ++d) T.p[ii][r][d] = (float)P[r][d];
    }
}

// --------------------------------- kernel ---------------------------------
__global__ __launch_bounds__(NTHREADS, 2) void BSL_25898652795515_kernel(
    const PTab T,                     // 3.5 KB const bank
    const float* __restrict__ X,      // (4096, 256)
    const float* __restrict__ C,      // (64, 256)
    const float* __restrict__ bias,   // (256,)
    float* __restrict__ out)          // (4096, 256)
{
    __shared__ float4 sT[TABN];       // 28 KB folded coefficient tile

    const int tile = blockIdx.y;      // feature tile 0..7
    const int f0   = tile * 32;
    const int row0 = blockIdx.x * ROWS_PER_BLOCK;
    const int tid  = threadIdx.x;
    const int lane = tid & 31;
    const int wrp  = tid >> 5;        // 0..15
    const int f    = f0 + lane;

    // ---- prefetch X rows (4-deep MLP; DRAM latency overlaps the fold) ----
    float xv[4];
    #pragma unroll
    for (int it = 0; it < 4; ++it)
        xv[it] = X[(row0 + it * 16 + wrp) * NF + f];

    // ---- fold (once per block): fully unrolled, all 16 LDGs batched ----
    // entry e = tid + k*512 (k=0..3), predicated on e < TABN.
    // ii = e>>5 is warp-uniform -> P reads on the uniform const port.
    {
        float c0[4], c1[4], c2[4], c3[4], bb[4];
        int   iiE[4], lnE[4];
        bool  act[4];
        #pragma unroll
        for (int k = 0; k < 4; ++k) {
            const int e = tid + k * NTHREADS;
            act[k] = (e < TABN);
            const int ec = act[k] ? e : (TABN - 1);
            iiE[k] = ec >> 5;
            lnE[k] = ec & 31;
            c0[k] = __ldg(&C[(iiE[k] + 3) * NF + f0 + lnE[k]]);
            c1[k] = __ldg(&C[(iiE[k] + 4) * NF + f0 + lnE[k]]);
            c2[k] = __ldg(&C[(iiE[k] + 5) * NF + f0 + lnE[k]]);
            c3[k] = __ldg(&C[(iiE[k] + 6) * NF + f0 + lnE[k]]);
            bb[k] = __ldg(&bias[f0 + lnE[k]]);
        }
        #pragma unroll
        for (int k = 0; k < 4; ++k) {
            if (!act[k]) continue;
            const int ii = iiE[k];
            float4 q;
            q.x = fmaf(T.p[ii][0][0], c0[k], fmaf(T.p[ii][1][0], c1[k],
                  fmaf(T.p[ii][2][0], c2[k], fmaf(T.p[ii][3][0], c3[k], bb[k]))));
            q.y = fmaf(T.p[ii][0][1], c0[k], fmaf(T.p[ii][1][1], c1[k],
                  fmaf(T.p[ii][2][1], c2[k], T.p[ii][3][1] * c3[k])));
            q.z = fmaf(T.p[ii][0][2], c0[k], fmaf(T.p[ii][1][2], c1[k],
                  fmaf(T.p[ii][2][2], c2[k], T.p[ii][3][2] * c3[k])));
            q.w = fmaf(T.p[ii][0][3], c0[k], fmaf(T.p[ii][1][3], c1[k],
                  fmaf(T.p[ii][2][3], c2[k], T.p[ii][3][3] * c3[k])));
            sT[ii * 32 + lnE[k]] = q;
        }
    }
    __syncthreads();

    // ---- hot loop: cvt-free ii/u, conflict-free LDS.128 ----
    const float MAGIC = 8388608.0f;   // 2^23: spacing 1 over [2^23, 2^23+55]
    #pragma unroll
    for (int it = 0; it < 4; ++it) {
        const float m   = fmaf(xv[it], 55.0f, MAGIC);     // 2^23 + round(55x)
        const int   n   = __float_as_int(m) & 0x7FFFFF;   // n = round(55x)
        const float nf  = m - MAGIC;                      // (float)n, exact
        const float u0  = fmaf(xv[it], 55.0f, -nf);       // 55x - n in [-0.5,0.5]
        const bool  neg = (u0 < 0.0f);
        const int   ii  = n - (neg ? 1 : 0);              // floor(55x) in [0,54]
        const float u   = u0 + (neg ? 1.0f : 0.0f);
        // LDS.128: bank16 = lane -> conflict-free (ii stride 512 B)
        const float4 c = sT[ii * 32 + lane];
        out[(row0 + it * 16 + wrp) * NF + f] =
            fmaf(fmaf(fmaf(c.w, u, c.z), u, c.y), u, c.x);
    }
}

extern "C" void kernel_launch(void* const* d_in, const int* in_sizes, int n_in,
                              void* d_out, int out_size) {
    const float* x    = (const float*)d_in[0];   // (4096, 256)
    const float* ctrl = (const float*)d_in[1];   // (64, 256)
    const float* bias = (const float*)d_in[2];   // (256,)
    float* out = (float*)d_out;

    PTab T;
    make_ptab(T);   // host double math, knot-only, deterministic

    dim3 grid(NBATCH / ROWS_PER_BLOCK, NF / 32);   // (64, 8) = 512 blocks
    BSL_25898652795515_kernel<<<grid, NTHREADS>>>(T, x, ctrl, bias, out);
}

// round 13
// speedup vs baseline: 1.2657x; 1.2657x over previous
#include <cuda_runtime.h>

// B-spline layer, single fused kernel, float4-vectorized fold (shortest chain).
// out[b,f] = ((q3*u+q2)*u+q1)*u + q0,  u = 55x - ii, ii = floor(55x) in [0,54],
// q_d[ii,f] = sum_r P[ii][r][d] * C[ii+3+r, f]   (bias folded into q0).
// P = Cox-de Boor basis polynomial coefficients in local coord u, computed on
// the HOST in double (knot-only, deterministic), passed in the const bank.
//
// Fold: thread t < 440 owns (ii = t>>3, ln4 = (t&7)*4): 4x LDG.128 (C rows)
// + 1x float4 bias, all issued back-to-back (ONE exposed L2 round-trip),
// 64 independent FMAs, 4x STS.128. No loop.
//
// Hot loop (cvt-free): m = fmaf(x,55,2^23) -> mantissa = round(55x) exactly
// (spacing 1 in [2^23, 2^23+55]); branchless floor fixup from sign of 55x-n.
//
// Grid (32,8) = 256 blocks x 512 thr, 128 rows/block, 8-deep X prefetch.

#define NF 256
#define NBATCH 4096
#define NII 55
#define NTHREADS 512
#define ROWS_PER_BLOCK 128
#define TABN (NII * 32)           // 1760 float4
#define FOLD_THREADS (NII * 8)    // 440: one per (ii, 4-lane group)

struct PTab { float p[NII][4][4]; };

// ---------------- host-side knot/coefficient math (double) ----------------
static double knotD_h(int idx) {
    if (idx < 6)  return -0.002 + 0.0005 * (double)(idx - 3);
    if (idx > 61) return 1.001  + 0.0005 * (double)(idx - 62);
    return (double)(idx - 6) / 55.0;
}

static void make_ptab(PTab& T) {
    for (int ii = 0; ii < NII; ++ii) {
        const int j = ii + 6;
        double P[4][4] = {};
        P[0][0] = 1.0;
        const double x0 = (double)ii / 55.0;
        const double bs = 1.0 / 55.0;   // x = x0 + bs*u
        for (int k = 1; k <= 3; ++k) {
            double Q[4][4] = {};
            for (int r = 0; r <= k; ++r) {
                const int i = j - k + r;
                if (r >= 1) {
                    const double inv = 1.0 / (knotD_h(i + k) - knotD_h(i));
                    const double a = (x0 - knotD_h(i)) * inv;
                    const double b = bs * inv;
                    for (int d = 0; d < 4; ++d) {
                        Q[r][d] += a * P[r - 1][d];
                        if (d > 0) Q[r][d] += b * P[r - 1][d - 1];
                    }
                }
                if (r <= k - 1) {
                    const double inv = 1.0 / (knotD_h(i + k + 1) - knotD_h(i + 1));
                    const double a = (knotD_h(i + k + 1) - x0) * inv;
                    const double b = -bs * inv;
                    for (int d = 0; d < 4; ++d) {
                        Q[r][d] += a * P[r][d];
                        if (d > 0) Q[r][d] += b * P[r][d - 1];
                    }
                }
            }
            for (int r = 0; r < 4; ++r)
                for (int d = 0; d < 4; ++d) P[r][d] = Q[r][d];
        }
        for (int r = 0; r < 4; ++r)
            for (int d = 0; d < 4; ++d) T.p[ii][r][d] = (float)P[r][d];
    }
}

// --------------------------------- kernel ---------------------------------
__global__ __launch_bounds__(NTHREADS) void BSL_25898652795515_kernel(
    const PTab T,                     // 3.5 KB const bank
    const float* __restrict__ X,      // (4096, 256)
    const float* __restrict__ C,      // (64, 256)
    const float* __restrict__ bias,   // (256,)
    float* __restrict__ out)          // (4096, 256)
{
    __shared__ float4 sT[TABN];       // 28 KB folded coefficient tile

    const int tile = blockIdx.y;      // feature tile 0..7
    const int f0   = tile * 32;
    const int row0 = blockIdx.x * ROWS_PER_BLOCK;
    const int tid  = threadIdx.x;
    const int lane = tid & 31;
    const int wrp  = tid >> 5;        // 0..15
    const int f    = f0 + lane;

    // ---- prefetch X rows (8-deep MLP; DRAM latency overlaps the fold) ----
    float xv[8];
    #pragma unroll
    for (int it = 0; it < 8; ++it)
        xv[it] = X[(row0 + it * 16 + wrp) * NF + f];

    // ---- fold (once per block): 5 vector loads, one L2 round-trip ----
    if (tid < FOLD_THREADS) {
        const int ii  = tid >> 3;           // 0..54 (warp covers 4 ii rows)
        const int ln4 = (tid & 7) * 4;      // 0,4,...,28
        const float4 c0 = *(const float4*)&C[(ii + 3) * NF + f0 + ln4];
        const float4 c1 = *(const float4*)&C[(ii + 4) * NF + f0 + ln4];
        const float4 c2 = *(const float4*)&C[(ii + 5) * NF + f0 + ln4];
        const float4 c3 = *(const float4*)&C[(ii + 6) * NF + f0 + ln4];
        const float4 bb = *(const float4*)&bias[f0 + ln4];

        const float p00 = T.p[ii][0][0], p10 = T.p[ii][1][0], p20 = T.p[ii][2][0], p30 = T.p[ii][3][0];
        const float p01 = T.p[ii][0][1], p11 = T.p[ii][1][1], p21 = T.p[ii][2][1], p31 = T.p[ii][3][1];
        const float p02 = T.p[ii][0][2], p12 = T.p[ii][1][2], p22 = T.p[ii][2][2], p32 = T.p[ii][3][2];
        const float p03 = T.p[ii][0][3], p13 = T.p[ii][1][3], p23 = T.p[ii][2][3], p33 = T.p[ii][3][3];

        #pragma unroll
        for (int m = 0; m < 4; ++m) {
            const float a0 = (&c0.x)[m], a1 = (&c1.x)[m], a2 = (&c2.x)[m], a3 = (&c3.x)[m];
            float4 q;
            q.x = fmaf(p00, a0, fmaf(p10, a1, fmaf(p20, a2, fmaf(p30, a3, (&bb.x)[m]))));
            q.y = fmaf(p01, a0, fmaf(p11, a1, fmaf(p21, a2, p31 * a3)));
            q.z = fmaf(p02, a0, fmaf(p12, a1, fmaf(p22, a2, p32 * a3)));
            q.w = fmaf(p03, a0, fmaf(p13, a1, fmaf(p23, a2, p33 * a3)));
            sT[ii * 32 + ln4 + m] = q;
        }
    }
    __syncthreads();

    // ---- hot loop: cvt-free ii/u, conflict-free LDS.128 ----
    const float MAGIC = 8388608.0f;   // 2^23: spacing 1 over [2^23, 2^23+55]
    #pragma unroll
    for (int it = 0; it < 8; ++it) {
        const float m   = fmaf(xv[it], 55.0f, MAGIC);     // 2^23 + round(55x)
        const int   n   = __float_as_int(m) & 0x7FFFFF;   // n = round(55x)
        const float nf  = m - MAGIC;                      // (float)n, exact
        const float u0  = fmaf(xv[it], 55.0f, -nf);       // 55x - n in [-0.5,0.5]
        const bool  neg = (u0 < 0.0f);
        const int   ii  = n - (neg ? 1 : 0);              // floor(55x) in [0,54]
        const float u   = u0 + (neg ? 1.0f : 0.0f);
        // LDS.128: bank16 = lane -> conflict-free (ii stride 512 B)
        const float4 c = sT[ii * 32 + lane];
        out[(row0 + it * 16 + wrp) * NF + f] =
            fmaf(fmaf(fmaf(c.w, u, c.z), u, c.y), u, c.x);
    }
}

extern "C" void kernel_launch(void* const* d_in, const int* in_sizes, int n_in,
                              void* d_out, int out_size) {
    const float* x    = (const float*)d_in[0];   // (4096, 256)
    const float* ctrl = (const float*)d_in[1];   // (64, 256)
    const float* bias = (const float*)d_in[2];   // (256,)
    float* out = (float*)d_out;

    PTab T;
    make_ptab(T);   // host double math, knot-only, deterministic

    dim3 grid(NBATCH / ROWS_PER_BLOCK, NF / 32);   // (32, 8) = 256 blocks
    BSL_25898652795515_kernel<<<grid, NTHREADS>>>(T, x, ctrl, bias, out);
}